// round 9
// baseline (speedup 1.0000x reference)
#include <cuda_runtime.h>
#include <cuda_bf16.h>
#include <math.h>
#include <stdint.h>

#define B_  2
#define S_  2048
#define H_  2048
#define NH  16
#define NKV 4
#define HD  128
#define KV_DIM (NKV*HD)   // 512
#define M_  (B_*S_)       // 4096
#define NQKV (H_ + 2*KV_DIM)  // 3072

// fp32 scratch
__device__ float g_Q[M_ * H_];
__device__ float g_K[M_ * KV_DIM];
__device__ float g_V[M_ * KV_DIM];
__device__ float g_AO[M_ * H_];

// bf16 split operands
__device__ __nv_bfloat16 g_xh[M_ * H_],  g_xl[M_ * H_];
__device__ __nv_bfloat16 g_aoh[M_ * H_], g_aol[M_ * H_];
__device__ __nv_bfloat16 g_Qh[M_ * H_],     g_Ql[M_ * H_];
__device__ __nv_bfloat16 g_Kh[M_ * KV_DIM], g_Kl[M_ * KV_DIM];
__device__ __nv_bfloat16 g_Vth[M_ * KV_DIM], g_Vtl[M_ * KV_DIM];
// Concatenated transposed split weights [3072][2048] (wq rows 0-2047, wk 2048-2559, wv 2560-3071)
__device__ __nv_bfloat16 g_wqkvh[NQKV * H_], g_wqkvl[NQKV * H_];
__device__ __nv_bfloat16 g_woh[H_ * H_],     g_wol[H_ * H_];

__device__ __forceinline__ unsigned pack_bf16(float lo, float hi) {
    unsigned d;
    asm("cvt.rn.bf16x2.f32 %0, %1, %2;" : "=r"(d) : "f"(hi), "f"(lo));
    return d;
}

__device__ __forceinline__ unsigned smem_u32(const void* p) {
    return (unsigned)__cvta_generic_to_shared(p);
}

#define LDSM_X4(r0, r1, r2, r3, addr) \
    asm volatile("ldmatrix.sync.aligned.m8n8.x4.shared.b16 {%0,%1,%2,%3}, [%4];" \
        : "=r"(r0), "=r"(r1), "=r"(r2), "=r"(r3) : "r"(addr))

#define CP_ASYNC16(dst, src) \
    asm volatile("cp.async.cg.shared.global [%0], [%1], 16;" :: "r"(dst), "l"(src) : "memory")
#define CP_COMMIT()  asm volatile("cp.async.commit_group;" ::: "memory")
#define CP_WAIT1()   asm volatile("cp.async.wait_group 1;" ::: "memory")

// ---------------------------------------------------------------------------
// Elementwise split: fp32 -> bf16 hi + bf16 lo
// ---------------------------------------------------------------------------
__global__ void split_kernel(const float* __restrict__ in,
                             __nv_bfloat16* __restrict__ hi,
                             __nv_bfloat16* __restrict__ lo, int n)
{
    int i = blockIdx.x * blockDim.x + threadIdx.x;
    if (i >= n) return;
    float x = in[i];
    __nv_bfloat16 h = __float2bfloat16(x);
    hi[i] = h;
    lo[i] = __float2bfloat16(x - __bfloat162float(h));
}

// ---------------------------------------------------------------------------
// Transpose + split: W[K][N] fp32 -> Th/Tl[N][K] bf16
// ---------------------------------------------------------------------------
__global__ void tsplit_kernel(const float* __restrict__ W,
                              __nv_bfloat16* __restrict__ Th,
                              __nv_bfloat16* __restrict__ Tl, int K, int N)
{
    __shared__ float tile[32][33];
    const int n0 = blockIdx.x * 32;
    const int k0 = blockIdx.y * 32;
    const int tx = threadIdx.x, ty = threadIdx.y;  // 32x8
#pragma unroll
    for (int r = 0; r < 32; r += 8)
        tile[ty + r][tx] = W[(size_t)(k0 + ty + r) * N + n0 + tx];
    __syncthreads();
#pragma unroll
    for (int r = 0; r < 32; r += 8) {
        float v = tile[tx][ty + r];
        __nv_bfloat16 h = __float2bfloat16(v);
        size_t o = (size_t)(n0 + ty + r) * K + k0 + tx;
        Th[o] = h;
        Tl[o] = __float2bfloat16(v - __bfloat162float(h));
    }
}

// ---------------------------------------------------------------------------
// RoPE + split
// ---------------------------------------------------------------------------
__global__ void rope_split_kernel(const float* __restrict__ buf,
                                  const float* __restrict__ ct,
                                  const float* __restrict__ st,
                                  int nheads,
                                  __nv_bfloat16* __restrict__ hi,
                                  __nv_bfloat16* __restrict__ lo)
{
    int i = blockIdx.x * blockDim.x + threadIdx.x;
    int total = M_ * nheads * 64;
    if (i >= total) return;
    int d   = i & 63;
    int h   = (i >> 6) % nheads;
    int row = i / (64 * nheads);
    int s   = row & (S_ - 1);
    float c  = ct[s * 64 + d];
    float sn = st[s * 64 + d];
    size_t o = (size_t)row * (nheads * HD) + h * HD + d;
    float x1 = buf[o], x2 = buf[o + 64];
    float y1 = x1 * c - x2 * sn;
    float y2 = x2 * c + x1 * sn;
    __nv_bfloat16 h1 = __float2bfloat16(y1);
    __nv_bfloat16 h2 = __float2bfloat16(y2);
    hi[o]      = h1;
    hi[o + 64] = h2;
    lo[o]      = __float2bfloat16(y1 - __bfloat162float(h1));
    lo[o + 64] = __float2bfloat16(y2 - __bfloat162float(h2));
}

// ---------------------------------------------------------------------------
// V split + transpose
// ---------------------------------------------------------------------------
__global__ void vsplit_t_kernel(const float* __restrict__ V,
                                __nv_bfloat16* __restrict__ Th,
                                __nv_bfloat16* __restrict__ Tl)
{
    __shared__ float tile[32][33];
    const int s0 = blockIdx.x * 32;
    const int d0 = blockIdx.y * 32;
    const int bk = blockIdx.z;           // b*NKV + kvh
    const int b  = bk / NKV;
    const int kvh = bk % NKV;
    const int tx = threadIdx.x, ty = threadIdx.y;  // 32x8
#pragma unroll
    for (int r = 0; r < 32; r += 8)
        tile[ty + r][tx] = V[(size_t)(b * S_ + s0 + ty + r) * KV_DIM + kvh * HD + d0 + tx];
    __syncthreads();
#pragma unroll
    for (int r = 0; r < 32; r += 8) {
        float v = tile[tx][ty + r];
        __nv_bfloat16 h = __float2bfloat16(v);
        size_t o = (size_t)(bk * HD + d0 + ty + r) * S_ + s0 + tx;
        Th[o] = h;
        Tl[o] = __float2bfloat16(v - __bfloat162float(h));
    }
}

// ---------------------------------------------------------------------------
// bf16x3 GEMM, cp.async 2-stage pipeline + ldmatrix.
// C[M,Ntot] = A[M,K] @ Bt^T, Bt = concat split weights [Ntot][K].
// Output split into up to 3 segments (Q/K/V) by blockIdx.x tile index.
// 128x128 CTA tile, BK=32, 8 warps (2x4) each 64x32, m16n8k16 bf16x3.
// ---------------------------------------------------------------------------
#define TILE_BYTES  (128 * 40 * 2)       // 10240
#define STAGE_BYTES (4 * TILE_BYTES)     // 40960

__global__ __launch_bounds__(256, 2) void bf16x3_gemm_pipe(
    const __nv_bfloat16* __restrict__ Ah, const __nv_bfloat16* __restrict__ Al,
    const __nv_bfloat16* __restrict__ Bth, const __nv_bfloat16* __restrict__ Btl,
    float* __restrict__ C0, float* __restrict__ C1, float* __restrict__ C2,
    int t0, int t1, int ldc0, int ldc1, int ldc2, int K)
{
    extern __shared__ unsigned char smem_raw[];
    const unsigned sbase = smem_u32(smem_raw);

    const int tid  = threadIdx.x;
    const int lane = tid & 31;
    const int warp = tid >> 5;
    const int g = lane >> 2;
    const int t = lane & 3;
    const int wm = (warp & 1) * 64;
    const int wn = (warp >> 1) * 32;

    const int bx   = blockIdx.x;
    const int brow = blockIdx.y * 128;
    const int bcolB = bx * 128;          // within concatenated B rows

    float* C; int ldc; int ccol;
    if (bx < t0)           { C = C0; ldc = ldc0; ccol = bx * 128; }
    else if (bx < t0 + t1) { C = C1; ldc = ldc1; ccol = (bx - t0) * 128; }
    else                   { C = C2; ldc = ldc2; ccol = (bx - t0 - t1) * 128; }

    // loader mapping: row = tid>>1, 16-element segment = (tid&1)*16
    const int lrow = tid >> 1;
    const int lce  = (tid & 1) * 16;
    const __nv_bfloat16* g0 = Ah  + (size_t)(brow + lrow) * K + lce;
    const __nv_bfloat16* g1 = Al  + (size_t)(brow + lrow) * K + lce;
    const __nv_bfloat16* g2 = Bth + (size_t)(bcolB + lrow) * K + lce;
    const __nv_bfloat16* g3 = Btl + (size_t)(bcolB + lrow) * K + lce;
    const unsigned dbase = (unsigned)lrow * 80u + (unsigned)lce * 2u;

#define LOAD_STAGE(s, k0) do {                                                  \
    unsigned db = sbase + (unsigned)(s) * STAGE_BYTES + dbase;                  \
    CP_ASYNC16(db,                        g0 + (k0));                           \
    CP_ASYNC16(db + 16,                   g0 + (k0) + 8);                       \
    CP_ASYNC16(db + TILE_BYTES,           g1 + (k0));                           \
    CP_ASYNC16(db + TILE_BYTES + 16,      g1 + (k0) + 8);                       \
    CP_ASYNC16(db + 2 * TILE_BYTES,       g2 + (k0));                           \
    CP_ASYNC16(db + 2 * TILE_BYTES + 16,  g2 + (k0) + 8);                       \
    CP_ASYNC16(db + 3 * TILE_BYTES,       g3 + (k0));                           \
    CP_ASYNC16(db + 3 * TILE_BYTES + 16,  g3 + (k0) + 8);                       \
} while (0)

    // ldmatrix per-lane base addresses (row stride 80 B)
    const unsigned aoff = (unsigned)((wm + (lane & 7) + ((lane >> 3) & 1) * 8) * 80
                                     + ((lane >> 4) & 1) * 16);
    const unsigned boff = (unsigned)((wn + (lane & 7) + ((lane >> 4) & 1) * 8) * 80
                                     + ((lane >> 3) & 1) * 16);

    float acc[4][4][4];
#pragma unroll
    for (int i = 0; i < 4; i++)
#pragma unroll
        for (int j = 0; j < 4; j++)
#pragma unroll
            for (int c = 0; c < 4; c++) acc[i][j][c] = 0.f;

    LOAD_STAGE(0, 0);
    CP_COMMIT();
    LOAD_STAGE(1, 32);
    CP_COMMIT();

    const int niter = K / 32;
    for (int it = 0; it < niter; it++) {
        CP_WAIT1();
        __syncthreads();
        const int s = it & 1;
        const unsigned sb = sbase + (unsigned)s * STAGE_BYTES;
        const unsigned aAsh = sb + aoff;
        const unsigned aAsl = sb + TILE_BYTES + aoff;
        const unsigned aBsh = sb + 2 * TILE_BYTES + boff;
        const unsigned aBsl = sb + 3 * TILE_BYTES + boff;

#pragma unroll
        for (int ks = 0; ks < 32; ks += 16) {
            const unsigned ko = (unsigned)(ks * 2);
            unsigned ah[4][4], al[4][4], bh[4][2], bl[4][2];
#pragma unroll
            for (int i = 0; i < 4; i++) {
                LDSM_X4(ah[i][0], ah[i][1], ah[i][2], ah[i][3], aAsh + (unsigned)(i * 16 * 80) + ko);
                LDSM_X4(al[i][0], al[i][1], al[i][2], al[i][3], aAsl + (unsigned)(i * 16 * 80) + ko);
            }
#pragma unroll
            for (int jp = 0; jp < 2; jp++) {
                LDSM_X4(bh[2 * jp][0], bh[2 * jp][1], bh[2 * jp + 1][0], bh[2 * jp + 1][1],
                        aBsh + (unsigned)(jp * 16 * 80) + ko);
                LDSM_X4(bl[2 * jp][0], bl[2 * jp][1], bl[2 * jp + 1][0], bl[2 * jp + 1][1],
                        aBsl + (unsigned)(jp * 16 * 80) + ko);
            }
#pragma unroll
            for (int i = 0; i < 4; i++)
#pragma unroll
                for (int j = 0; j < 4; j++) {
                    float* c = acc[i][j];
                    asm volatile(
                        "mma.sync.aligned.m16n8k16.row.col.f32.bf16.bf16.f32 "
                        "{%0,%1,%2,%3}, {%4,%5,%6,%7}, {%8,%9}, {%0,%1,%2,%3};"
                        : "+f"(c[0]), "+f"(c[1]), "+f"(c[2]), "+f"(c[3])
                        : "r"(ah[i][0]), "r"(ah[i][1]), "r"(ah[i][2]), "r"(ah[i][3]),
                          "r"(bh[j][0]), "r"(bh[j][1]));
                    asm volatile(
                        "mma.sync.aligned.m16n8k16.row.col.f32.bf16.bf16.f32 "
                        "{%0,%1,%2,%3}, {%4,%5,%6,%7}, {%8,%9}, {%0,%1,%2,%3};"
                        : "+f"(c[0]), "+f"(c[1]), "+f"(c[2]), "+f"(c[3])
                        : "r"(ah[i][0]), "r"(ah[i][1]), "r"(ah[i][2]), "r"(ah[i][3]),
                          "r"(bl[j][0]), "r"(bl[j][1]));
                    asm volatile(
                        "mma.sync.aligned.m16n8k16.row.col.f32.bf16.bf16.f32 "
                        "{%0,%1,%2,%3}, {%4,%5,%6,%7}, {%8,%9}, {%0,%1,%2,%3};"
                        : "+f"(c[0]), "+f"(c[1]), "+f"(c[2]), "+f"(c[3])
                        : "r"(al[i][0]), "r"(al[i][1]), "r"(al[i][2]), "r"(al[i][3]),
                          "r"(bh[j][0]), "r"(bh[j][1]));
                }
        }
        __syncthreads();
        const int kn = (it + 2) * 32;
        if (kn < K) LOAD_STAGE(s, kn);
        CP_COMMIT();
    }
#undef LOAD_STAGE

#pragma unroll
    for (int i = 0; i < 4; i++) {
        const int r0 = brow + wm + i * 16 + g;
#pragma unroll
        for (int j = 0; j < 4; j++) {
            const int cc = ccol + wn + j * 8 + 2 * t;
            *(float2*)(C + (size_t)r0 * ldc + cc)       = make_float2(acc[i][j][0], acc[i][j][1]);
            *(float2*)(C + (size_t)(r0 + 8) * ldc + cc) = make_float2(acc[i][j][2], acc[i][j][3]);
        }
    }
}

// ---------------------------------------------------------------------------
// Tensor-core flash attention (validated R6/R8, unchanged)
// ---------------------------------------------------------------------------
#define KROW 136
#define VROW 72

__global__ __launch_bounds__(256) void flash_mma_kernel(
    const __nv_bfloat16* __restrict__ Qh, const __nv_bfloat16* __restrict__ Ql,
    const __nv_bfloat16* __restrict__ Kh, const __nv_bfloat16* __restrict__ Kl,
    const __nv_bfloat16* __restrict__ Vth, const __nv_bfloat16* __restrict__ Vtl,
    float* __restrict__ O)
{
    extern __shared__ __nv_bfloat16 smem_bf[];
    __nv_bfloat16* kh = smem_bf;
    __nv_bfloat16* kl = kh + 64 * KROW;
    __nv_bfloat16* vh = kl + 64 * KROW;
    __nv_bfloat16* vl = vh + 128 * VROW;

    const int qb  = (int)gridDim.x - 1 - (int)blockIdx.x;
    const int bh  = blockIdx.y;
    const int b   = bh >> 4;
    const int h   = bh & 15;
    const int kvh = h >> 2;

    const int tid  = threadIdx.x;
    const int lane = tid & 31;
    const int w    = tid >> 5;
    const int g    = lane >> 2;
    const int t    = lane & 3;
    const int m0   = w * 16;

    unsigned qfh[8][4], qfl[8][4];
    {
        const __nv_bfloat16* Qb  = Qh + ((size_t)(b * S_ + qb * 128 + m0)) * H_ + h * HD;
        const __nv_bfloat16* Qlb = Ql + ((size_t)(b * S_ + qb * 128 + m0)) * H_ + h * HD;
#pragma unroll
        for (int kc = 0; kc < 8; kc++) {
            int c0 = kc * 16 + 2 * t;
            qfh[kc][0] = *(const unsigned*)(Qb  + (size_t)g * H_ + c0);
            qfh[kc][1] = *(const unsigned*)(Qb  + (size_t)(g + 8) * H_ + c0);
            qfh[kc][2] = *(const unsigned*)(Qb  + (size_t)g * H_ + c0 + 8);
            qfh[kc][3] = *(const unsigned*)(Qb  + (size_t)(g + 8) * H_ + c0 + 8);
            qfl[kc][0] = *(const unsigned*)(Qlb + (size_t)g * H_ + c0);
            qfl[kc][1] = *(const unsigned*)(Qlb + (size_t)(g + 8) * H_ + c0);
            qfl[kc][2] = *(const unsigned*)(Qlb + (size_t)g * H_ + c0 + 8);
            qfl[kc][3] = *(const unsigned*)(Qlb + (size_t)(g + 8) * H_ + c0 + 8);
        }
    }

    float oacc[16][4];
#pragma unroll
    for (int jn = 0; jn < 16; jn++)
#pragma unroll
        for (int c = 0; c < 4; c++) oacc[jn][c] = 0.f;
    float mrow0 = -INFINITY, mrow1 = -INFINITY;
    float lrow0 = 0.f, lrow1 = 0.f;

    const float scale = 0.08838834764831845f;
    const int njt = 2 * qb + 2;

    for (int j = 0; j < njt; j++) {
        __syncthreads();
        {
            const __nv_bfloat16* Kb  = Kh + (size_t)(b * S_ + j * 64) * KV_DIM + kvh * HD;
            const __nv_bfloat16* Klb = Kl + (size_t)(b * S_ + j * 64) * KV_DIM + kvh * HD;
#pragma unroll
            for (int it = 0; it < 4; it++) {
                int idx = tid + it * 256;
                int r  = idx >> 4;
                int c8 = (idx & 15) * 8;
                *(uint4*)&kh[r * KROW + c8] = *(const uint4*)(Kb  + (size_t)r * KV_DIM + c8);
                *(uint4*)&kl[r * KROW + c8] = *(const uint4*)(Klb + (size_t)r * KV_DIM + c8);
            }
            const __nv_bfloat16* Vb  = Vth + ((size_t)((b * NKV + kvh) * HD)) * S_ + j * 64;
            const __nv_bfloat16* Vlb = Vtl + ((size_t)((b * NKV + kvh) * HD)) * S_ + j * 64;
#pragma unroll
            for (int it = 0; it < 4; it++) {
                int idx = tid + it * 256;
                int r  = idx >> 3;
                int c8 = (idx & 7) * 8;
                *(uint4*)&vh[r * VROW + c8] = *(const uint4*)(Vb  + (size_t)r * S_ + c8);
                *(uint4*)&vl[r * VROW + c8] = *(const uint4*)(Vlb + (size_t)r * S_ + c8);
            }
        }
        __syncthreads();

        float sf[8][4];
#pragma unroll
        for (int jn = 0; jn < 8; jn++)
#pragma unroll
            for (int c = 0; c < 4; c++) sf[jn][c] = 0.f;

#pragma unroll
        for (int jn = 0; jn < 8; jn++) {
            const int n0 = jn * 8;
#pragma unroll
            for (int kc = 0; kc < 8; kc++) {
                const int ck = kc * 16 + 2 * t;
                unsigned b0h = *(const unsigned*)&kh[(n0 + g) * KROW + ck];
                unsigned b1h = *(const unsigned*)&kh[(n0 + g) * KROW + ck + 8];
                unsigned b0l = *(const unsigned*)&kl[(n0 + g) * KROW + ck];
                unsigned b1l = *(const unsigned*)&kl[(n0 + g) * KROW + ck + 8];
                float* c = sf[jn];
                asm volatile(
                    "mma.sync.aligned.m16n8k16.row.col.f32.bf16.bf16.f32 "
                    "{%0,%1,%2,%3}, {%4,%5,%6,%7}, {%8,%9}, {%0,%1,%2,%3};"
                    : "+f"(c[0]), "+f"(c[1]), "+f"(c[2]), "+f"(c[3])
                    : "r"(qfh[kc][0]), "r"(qfh[kc][1]), "r"(qfh[kc][2]), "r"(qfh[kc][3]),
                      "r"(b0h), "r"(b1h));
                asm volatile(
                    "mma.sync.aligned.m16n8k16.row.col.f32.bf16.bf16.f32 "
                    "{%0,%1,%2,%3}, {%4,%5,%6,%7}, {%8,%9}, {%0,%1,%2,%3};"
                    : "+f"(c[0]), "+f"(c[1]), "+f"(c[2]), "+f"(c[3])
                    : "r"(qfh[kc][0]), "r"(qfh[kc][1]), "r"(qfh[kc][2]), "r"(qfh[kc][3]),
                      "r"(b0l), "r"(b1l));
                asm volatile(
                    "mma.sync.aligned.m16n8k16.row.col.f32.bf16.bf16.f32 "
                    "{%0,%1,%2,%3}, {%4,%5,%6,%7}, {%8,%9}, {%0,%1,%2,%3};"
                    : "+f"(c[0]), "+f"(c[1]), "+f"(c[2]), "+f"(c[3])
                    : "r"(qfl[kc][0]), "r"(qfl[kc][1]), "r"(qfl[kc][2]), "r"(qfl[kc][3]),
                      "r"(b0h), "r"(b1h));
            }
        }

        const int row0 = qb * 128 + m0 + g;
        const int row1 = row0 + 8;
        const bool need_mask = (j >= 2 * qb);
#pragma unroll
        for (int jn = 0; jn < 8; jn++) {
            const int cbase = j * 64 + jn * 8 + 2 * t;
#pragma unroll
            for (int c = 0; c < 4; c++) sf[jn][c] *= scale;
            if (need_mask) {
                if (cbase     > row0) sf[jn][0] = -1e30f;
                if (cbase + 1 > row0) sf[jn][1] = -1e30f;
                if (cbase     > row1) sf[jn][2] = -1e30f;
                if (cbase + 1 > row1) sf[jn][3] = -1e30f;
            }
        }

        float mx0 = -INFINITY, mx1 = -INFINITY;
#pragma unroll
        for (int jn = 0; jn < 8; jn++) {
            mx0 = fmaxf(mx0, fmaxf(sf[jn][0], sf[jn][1]));
            mx1 = fmaxf(mx1, fmaxf(sf[jn][2], sf[jn][3]));
        }
        mx0 = fmaxf(mx0, __shfl_xor_sync(0xffffffffu, mx0, 1));
        mx0 = fmaxf(mx0, __shfl_xor_sync(0xffffffffu, mx0, 2));
        mx1 = fmaxf(mx1, __shfl_xor_sync(0xffffffffu, mx1, 1));
        mx1 = fmaxf(mx1, __shfl_xor_sync(0xffffffffu, mx1, 2));
        float mn0 = fmaxf(mrow0, mx0);
        float mn1 = fmaxf(mrow1, mx1);
        float f0 = __expf(mrow0 - mn0);
        float f1 = __expf(mrow1 - mn1);
        mrow0 = mn0; mrow1 = mn1;

        float sum0 = 0.f, sum1 = 0.f;
#pragma unroll
        for (int jn = 0; jn < 8; jn++) {
            sf[jn][0] = __expf(sf[jn][0] - mn0);
            sf[jn][1] = __expf(sf[jn][1] - mn0);
            sf[jn][2] = __expf(sf[jn][2] - mn1);
            sf[jn][3] = __expf(sf[jn][3] - mn1);
            sum0 += sf[jn][0] + sf[jn][1];
            sum1 += sf[jn][2] + sf[jn][3];
        }
        sum0 += __shfl_xor_sync(0xffffffffu, sum0, 1);
        sum0 += __shfl_xor_sync(0xffffffffu, sum0, 2);
        sum1 += __shfl_xor_sync(0xffffffffu, sum1, 1);
        sum1 += __shfl_xor_sync(0xffffffffu, sum1, 2);
        lrow0 = lrow0 * f0 + sum0;
        lrow1 = lrow1 * f1 + sum1;

#pragma unroll
        for (int jn = 0; jn < 16; jn++) {
            oacc[jn][0] *= f0; oacc[jn][1] *= f0;
            oacc[jn][2] *= f1; oacc[jn][3] *= f1;
        }

#pragma unroll
        for (int kc = 0; kc < 4; kc++) {
            const int j0 = 2 * kc, j1 = 2 * kc + 1;
            unsigned a0h = pack_bf16(sf[j0][0], sf[j0][1]);
            unsigned a1h = pack_bf16(sf[j0][2], sf[j0][3]);
            unsigned a2h = pack_bf16(sf[j1][0], sf[j1][1]);
            unsigned a3h = pack_bf16(sf[j1][2], sf[j1][3]);
            unsigned a0l = pack_bf16(sf[j0][0] - __uint_as_float(a0h << 16),
                                     sf[j0][1] - __uint_as_float(a0h & 0xffff0000u));
            unsigned a1l = pack_bf16(sf[j0][2] - __uint_as_float(a1h << 16),
                                     sf[j0][3] - __uint_as_float(a1h & 0xffff0000u));
            unsigned a2l = pack_bf16(sf[j1][0] - __uint_as_float(a2h << 16),
                                     sf[j1][1] - __uint_as_float(a2h & 0xffff0000u));
            unsigned a3l = pack_bf16(sf[j1][2] - __uint_as_float(a3h << 16),
                                     sf[j1][3] - __uint_as_float(a3h & 0xffff0000u));
            const int ck = kc * 16 + 2 * t;
#pragma unroll
            for (int jn = 0; jn < 16; jn++) {
                const int n0 = jn * 8;
                unsigned b0h = *(const unsigned*)&vh[(n0 + g) * VROW + ck];
                unsigned b1h = *(const unsigned*)&vh[(n0 + g) * VROW + ck + 8];
                unsigned b0l = *(const unsigned*)&vl[(n0 + g) * VROW + ck];
                unsigned b1l = *(const unsigned*)&vl[(n0 + g) * VROW + ck + 8];
                float* c = oacc[jn];
                asm volatile(
                    "mma.sync.aligned.m16n8k16.row.col.f32.bf16.bf16.f32 "
                    "{%0,%1,%2,%3}, {%4,%5,%6,%7}, {%8,%9}, {%0,%1,%2,%3};"
                    : "+f"(c[0]), "+f"(c[1]), "+f"(c[2]), "+f"(c[3])
                    : "r"(a0h), "r"(a1h), "r"(a2h), "r"(a3h),
                      "r"(b0h), "r"(b1h));
                asm volatile(
                    "mma.sync.aligned.m16n8k16.row.col.f32.bf16.bf16.f32 "
                    "{%0,%1,%2,%3}, {%4,%5,%6,%7}, {%8,%9}, {%0,%1,%2,%3};"
                    : "+f"(c[0]), "+f"(c[1]), "+f"(c[2]), "+f"(c[3])
                    : "r"(a0h), "r"(a1h), "r"(a2h), "r"(a3h),
                      "r"(b0l), "r"(b1l));
                asm volatile(
                    "mma.sync.aligned.m16n8k16.row.col.f32.bf16.bf16.f32 "
                    "{%0,%1,%2,%3}, {%4,%5,%6,%7}, {%8,%9}, {%0,%1,%2,%3};"
                    : "+f"(c[0]), "+f"(c[1]), "+f"(c[2]), "+f"(c[3])
                    : "r"(a0l), "r"(a1l), "r"(a2l), "r"(a3l),
                      "r"(b0h), "r"(b1h));
            }
        }
    }

    {
        float inv0 = 1.f / lrow0;
        float inv1 = 1.f / lrow1;
        float* Ob = O + ((size_t)(b * S_ + qb * 128 + m0 + g)) * H_ + h * HD;
#pragma unroll
        for (int jn = 0; jn < 16; jn++) {
            const int cc = jn * 8 + 2 * t;
            *(float2*)(Ob + cc)          = make_float2(oacc[jn][0] * inv0, oacc[jn][1] * inv0);
            *(float2*)(Ob + 8 * H_ + cc) = make_float2(oacc[jn][2] * inv1, oacc[jn][3] * inv1);
        }
    }
}

// ---------------------------------------------------------------------------
extern "C" void kernel_launch(void* const* d_in, const int* in_sizes, int n_in,
                              void* d_out, int out_size)
{
    const float* x  = (const float*)d_in[0];
    const float* rc = (const float*)d_in[1];
    const float* rs = (const float*)d_in[2];
    const float* wq = (const float*)d_in[4];
    const float* wk = (const float*)d_in[5];
    const float* wv = (const float*)d_in[6];
    const float* wo = (const float*)d_in[7];
    float* out = (float*)d_out;

    float *Q, *K, *V, *AO;
    cudaGetSymbolAddress((void**)&Q,  g_Q);
    cudaGetSymbolAddress((void**)&K,  g_K);
    cudaGetSymbolAddress((void**)&V,  g_V);
    cudaGetSymbolAddress((void**)&AO, g_AO);

    __nv_bfloat16 *xh, *xl, *aoh, *aol;
    __nv_bfloat16 *qh, *ql, *kh, *kl, *vth, *vtl;
    __nv_bfloat16 *wqkvh, *wqkvl, *woh, *wol;
    cudaGetSymbolAddress((void**)&xh,  g_xh);
    cudaGetSymbolAddress((void**)&xl,  g_xl);
    cudaGetSymbolAddress((void**)&aoh, g_aoh);
    cudaGetSymbolAddress((void**)&aol, g_aol);
    cudaGetSymbolAddress((void**)&qh,  g_Qh);
    cudaGetSymbolAddress((void**)&ql,  g_Ql);
    cudaGetSymbolAddress((void**)&kh,  g_Kh);
    cudaGetSymbolAddress((void**)&kl,  g_Kl);
    cudaGetSymbolAddress((void**)&vth, g_Vth);
    cudaGetSymbolAddress((void**)&vtl, g_Vtl);
    cudaGetSymbolAddress((void**)&wqkvh, g_wqkvh);
    cudaGetSymbolAddress((void**)&wqkvl, g_wqkvl);
    cudaGetSymbolAddress((void**)&woh, g_woh);
    cudaGetSymbolAddress((void**)&wol, g_wol);

    // Prep: transpose+split weights (into concatenated QKV buffer), split x
    dim3 tsb(32, 8);
    tsplit_kernel<<<dim3(H_ / 32,      H_ / 32), tsb>>>(wq, wqkvh,                       wqkvl,                       H_, H_);
    tsplit_kernel<<<dim3(KV_DIM / 32,  H_ / 32), tsb>>>(wk, wqkvh + (size_t)H_ * H_,     wqkvl + (size_t)H_ * H_,     H_, KV_DIM);
    tsplit_kernel<<<dim3(KV_DIM / 32,  H_ / 32), tsb>>>(wv, wqkvh + (size_t)(H_ + KV_DIM) * H_,
                                                        wqkvl + (size_t)(H_ + KV_DIM) * H_, H_, KV_DIM);
    tsplit_kernel<<<dim3(H_ / 32,      H_ / 32), tsb>>>(wo, woh, wol, H_, H_);
    split_kernel<<<(M_ * H_ + 255) / 256, 256>>>(x, xh, xl, M_ * H_);

    // Fused QKV projection (cp.async 2-stage pipelined bf16x3)
    const int gemm_smem = 2 * STAGE_BYTES;
    cudaFuncSetAttribute(bf16x3_gemm_pipe,
                         cudaFuncAttributeMaxDynamicSharedMemorySize, gemm_smem);
    bf16x3_gemm_pipe<<<dim3(NQKV / 128, M_ / 128), 256, gemm_smem>>>(
        xh, xl, wqkvh, wqkvl, Q, K, V,
        H_ / 128, KV_DIM / 128, H_, KV_DIM, KV_DIM, H_);

    // RoPE + split; V split + transpose
    {
        int nq = M_ * NH  * 64;
        int nk = M_ * NKV * 64;
        rope_split_kernel<<<(nq + 255) / 256, 256>>>(Q, rc, rs, NH,  qh, ql);
        rope_split_kernel<<<(nk + 255) / 256, 256>>>(K, rc, rs, NKV, kh, kl);
        vsplit_t_kernel<<<dim3(S_ / 32, HD / 32, B_ * NKV), tsb>>>(V, vth, vtl);
    }

    // Flash attention (mma.sync)
    {
        size_t shmem = (size_t)(2 * 64 * KROW + 2 * 128 * VROW) * sizeof(__nv_bfloat16);
        cudaFuncSetAttribute(flash_mma_kernel,
                             cudaFuncAttributeMaxDynamicSharedMemorySize,
                             (int)shmem);
        flash_mma_kernel<<<dim3(S_ / 128, B_ * NH), 256, shmem>>>(qh, ql, kh, kl, vth, vtl, AO);
    }

    // Output projection
    split_kernel<<<(M_ * H_ + 255) / 256, 256>>>(AO, aoh, aol, M_ * H_);
    bf16x3_gemm_pipe<<<dim3(H_ / 128, M_ / 128), 256, gemm_smem>>>(
        aoh, aol, woh, wol, out, out, out,
        H_ / 128, 0, H_, H_, H_, H_);
}

// round 10
// speedup vs baseline: 1.1987x; 1.1987x over previous
#include <cuda_runtime.h>
#include <cuda_bf16.h>
#include <math.h>
#include <stdint.h>

#define B_  2
#define S_  2048
#define H_  2048
#define NH  16
#define NKV 4
#define HD  128
#define KV_DIM (NKV*HD)   // 512
#define M_  (B_*S_)       // 4096
#define NQKV (H_ + 2*KV_DIM)  // 3072

// fp32 scratch
__device__ float g_Q[M_ * H_];
__device__ float g_K[M_ * KV_DIM];
__device__ float g_V[M_ * KV_DIM];
__device__ float g_AO[M_ * H_];

// bf16 split operands.
// GEMM operands use tiled-K layout: [K/64][rows][64] (tiles contiguous).
__device__ __nv_bfloat16 g_xh[M_ * H_],  g_xl[M_ * H_];     // tiled, rows=M_
__device__ __nv_bfloat16 g_aoh[M_ * H_], g_aol[M_ * H_];    // tiled, rows=M_
__device__ __nv_bfloat16 g_wqkvh[NQKV * H_], g_wqkvl[NQKV * H_]; // tiled, rows=NQKV
__device__ __nv_bfloat16 g_woh[H_ * H_],     g_wol[H_ * H_];     // tiled, rows=H_
// flash operands (row-major, unchanged)
__device__ __nv_bfloat16 g_Qh[M_ * H_],     g_Ql[M_ * H_];
__device__ __nv_bfloat16 g_Kh[M_ * KV_DIM], g_Kl[M_ * KV_DIM];
__device__ __nv_bfloat16 g_Vth[M_ * KV_DIM], g_Vtl[M_ * KV_DIM];

__device__ __forceinline__ unsigned pack_bf16(float lo, float hi) {
    unsigned d;
    asm("cvt.rn.bf16x2.f32 %0, %1, %2;" : "=r"(d) : "f"(hi), "f"(lo));
    return d;
}
__device__ __forceinline__ unsigned smem_u32(const void* p) {
    return (unsigned)__cvta_generic_to_shared(p);
}

#define LDSM_X4(r0, r1, r2, r3, addr) \
    asm volatile("ldmatrix.sync.aligned.m8n8.x4.shared.b16 {%0,%1,%2,%3}, [%4];" \
        : "=r"(r0), "=r"(r1), "=r"(r2), "=r"(r3) : "r"(addr))

#define CP_ASYNC16(dst, src) \
    asm volatile("cp.async.cg.shared.global [%0], [%1], 16;" :: "r"(dst), "l"(src) : "memory")
#define CP_COMMIT()  asm volatile("cp.async.commit_group;" ::: "memory")
#define CP_WAIT1()   asm volatile("cp.async.wait_group 1;" ::: "memory")

#define MMA_BF16(c, a0,a1,a2,a3, b0,b1) \
    asm volatile( \
        "mma.sync.aligned.m16n8k16.row.col.f32.bf16.bf16.f32 " \
        "{%0,%1,%2,%3}, {%4,%5,%6,%7}, {%8,%9}, {%0,%1,%2,%3};" \
        : "+f"((c)[0]), "+f"((c)[1]), "+f"((c)[2]), "+f"((c)[3]) \
        : "r"(a0), "r"(a1), "r"(a2), "r"(a3), "r"(b0), "r"(b1))

// ---------------------------------------------------------------------------
// Split x/AO into tiled-K layout [K/64][rows][64] (K = 2048 fixed)
// ---------------------------------------------------------------------------
__global__ void split_tiled_kernel(const float* __restrict__ in,
                                   __nv_bfloat16* __restrict__ hi,
                                   __nv_bfloat16* __restrict__ lo, int rows)
{
    int i = blockIdx.x * blockDim.x + threadIdx.x;
    if (i >= rows * H_) return;
    int row = i >> 11;         // /2048
    int k   = i & 2047;
    float x = in[i];
    __nv_bfloat16 h = __float2bfloat16(x);
    size_t o = (size_t)(k >> 6) * rows * 64 + (size_t)row * 64 + (k & 63);
    hi[o] = h;
    lo[o] = __float2bfloat16(x - __bfloat162float(h));
}

// ---------------------------------------------------------------------------
// Transpose + split: W[K][N] fp32 -> tiled [k/64][n_total rows][64] at n_base
// ---------------------------------------------------------------------------
__global__ void tsplit_tiled_kernel(const float* __restrict__ W,
                                    __nv_bfloat16* __restrict__ Th,
                                    __nv_bfloat16* __restrict__ Tl,
                                    int N, int n_base, int n_total)
{
    __shared__ float tile[32][33];
    const int n0 = blockIdx.x * 32;
    const int k0 = blockIdx.y * 32;
    const int tx = threadIdx.x, ty = threadIdx.y;  // 32x8
#pragma unroll
    for (int r = 0; r < 32; r += 8)
        tile[ty + r][tx] = W[(size_t)(k0 + ty + r) * N + n0 + tx];
    __syncthreads();
#pragma unroll
    for (int r = 0; r < 32; r += 8) {
        float v = tile[tx][ty + r];                 // W[k0+tx][n0+ty+r]
        __nv_bfloat16 h = __float2bfloat16(v);
        int k = k0 + tx;
        int n = n_base + n0 + ty + r;
        size_t o = (size_t)(k >> 6) * n_total * 64 + (size_t)n * 64 + (k & 63);
        Th[o] = h;
        Tl[o] = __float2bfloat16(v - __bfloat162float(h));
    }
}

// ---------------------------------------------------------------------------
// RoPE + split (row-major output, for flash)
// ---------------------------------------------------------------------------
__global__ void rope_split_kernel(const float* __restrict__ buf,
                                  const float* __restrict__ ct,
                                  const float* __restrict__ st,
                                  int nheads,
                                  __nv_bfloat16* __restrict__ hi,
                                  __nv_bfloat16* __restrict__ lo)
{
    int i = blockIdx.x * blockDim.x + threadIdx.x;
    int total = M_ * nheads * 64;
    if (i >= total) return;
    int d   = i & 63;
    int h   = (i >> 6) % nheads;
    int row = i / (64 * nheads);
    int s   = row & (S_ - 1);
    float c  = ct[s * 64 + d];
    float sn = st[s * 64 + d];
    size_t o = (size_t)row * (nheads * HD) + h * HD + d;
    float x1 = buf[o], x2 = buf[o + 64];
    float y1 = x1 * c - x2 * sn;
    float y2 = x2 * c + x1 * sn;
    __nv_bfloat16 h1 = __float2bfloat16(y1);
    __nv_bfloat16 h2 = __float2bfloat16(y2);
    hi[o]      = h1;
    hi[o + 64] = h2;
    lo[o]      = __float2bfloat16(y1 - __bfloat162float(h1));
    lo[o + 64] = __float2bfloat16(y2 - __bfloat162float(h2));
}

// ---------------------------------------------------------------------------
// V split + transpose (for flash)
// ---------------------------------------------------------------------------
__global__ void vsplit_t_kernel(const float* __restrict__ V,
                                __nv_bfloat16* __restrict__ Th,
                                __nv_bfloat16* __restrict__ Tl)
{
    __shared__ float tile[32][33];
    const int s0 = blockIdx.x * 32;
    const int d0 = blockIdx.y * 32;
    const int bk = blockIdx.z;
    const int b  = bk / NKV;
    const int kvh = bk % NKV;
    const int tx = threadIdx.x, ty = threadIdx.y;
#pragma unroll
    for (int r = 0; r < 32; r += 8)
        tile[ty + r][tx] = V[(size_t)(b * S_ + s0 + ty + r) * KV_DIM + kvh * HD + d0 + tx];
    __syncthreads();
#pragma unroll
    for (int r = 0; r < 32; r += 8) {
        float v = tile[tx][ty + r];
        __nv_bfloat16 h = __float2bfloat16(v);
        size_t o = (size_t)(bk * HD + d0 + ty + r) * S_ + s0 + tx;
        Th[o] = h;
        Tl[o] = __float2bfloat16(v - __bfloat162float(h));
    }
}

// ---------------------------------------------------------------------------
// bf16x3 GEMM, tiled-K operands, BK=64 stages, cp.async 2-stage, ldmatrix.
// Smem arrays [128 rows][128 B] with XOR-16B swizzle (c16 ^= row&7):
// coalesced cp.async stores AND conflict-free ldmatrix.
// 128x128 CTA tile, 8 warps (2x4) each 64x32, m16n8k16 bf16x3.
// ---------------------------------------------------------------------------
#define ARR_BYTES  16384u             // 128 * 128
#define STAGE_B    (4u * ARR_BYTES)   // 65536

__global__ __launch_bounds__(256) void bf16x3_gemm_tiled(
    const __nv_bfloat16* __restrict__ Ah, const __nv_bfloat16* __restrict__ Al,
    const __nv_bfloat16* __restrict__ Bh, const __nv_bfloat16* __restrict__ Bl,
    float* __restrict__ C0, float* __restrict__ C1, float* __restrict__ C2,
    int t0, int t1, int ldc0, int ldc1, int ldc2, int K, int An, int Bn)
{
    extern __shared__ unsigned char smem_raw[];
    const unsigned sbase = smem_u32(smem_raw);

    const int tid  = threadIdx.x;
    const int lane = tid & 31;
    const int warp = tid >> 5;
    const int g = lane >> 2;
    const int t = lane & 3;
    const int wm = (warp & 1) * 64;
    const int wn = (warp >> 1) * 32;

    const int bx   = blockIdx.x;
    const int brow = blockIdx.y * 128;
    const int bcolB = bx * 128;

    float* C; int ldc; int ccol;
    if (bx < t0)           { C = C0; ldc = ldc0; ccol = bx * 128; }
    else if (bx < t0 + t1) { C = C1; ldc = ldc1; ccol = (bx - t0) * 128; }
    else                   { C = C2; ldc = ldc2; ccol = (bx - t0 - t1) * 128; }

    // loader: 1024 16B-units per array; thread covers 4 per array.
    // unit u: r = u>>3 (row 0..127), c8 = u&7 (16B col). Global contiguous.
    const size_t aStride = (size_t)An * 64;   // elements per k-chunk (A)
    const size_t bStride = (size_t)Bn * 64;
    const __nv_bfloat16* aBaseH = Ah + (size_t)brow * 64;
    const __nv_bfloat16* aBaseL = Al + (size_t)brow * 64;
    const __nv_bfloat16* bBaseH = Bh + (size_t)bcolB * 64;
    const __nv_bfloat16* bBaseL = Bl + (size_t)bcolB * 64;

#define LOAD_STAGE(s, ch) do {                                                       \
    const unsigned sb = sbase + (unsigned)(s) * STAGE_B;                             \
    const size_t aoffg = (size_t)(ch) * aStride;                                     \
    const size_t boffg = (size_t)(ch) * bStride;                                     \
    _Pragma("unroll")                                                                \
    for (int i_ = 0; i_ < 4; i_++) {                                                 \
        int u  = tid + i_ * 256;                                                     \
        int r_ = u >> 3;                                                             \
        int c8 = u & 7;                                                              \
        unsigned d_ = (unsigned)(r_ * 128 + (((unsigned)c8 ^ ((unsigned)r_ & 7u)) << 4)); \
        size_t gsrc = (size_t)r_ * 64 + (size_t)c8 * 8;                              \
        CP_ASYNC16(sb + d_,                 aBaseH + aoffg + gsrc);                  \
        CP_ASYNC16(sb + ARR_BYTES + d_,     aBaseL + aoffg + gsrc);                  \
        CP_ASYNC16(sb + 2 * ARR_BYTES + d_, bBaseH + boffg + gsrc);                  \
        CP_ASYNC16(sb + 3 * ARR_BYTES + d_, bBaseL + boffg + gsrc);                  \
    }                                                                                \
} while (0)

    // ldmatrix per-lane addressing (row*128 + swizzled 16B col)
    const unsigned arow = (unsigned)(wm + (lane & 7) + ((lane >> 3) & 1) * 8);
    const unsigned ahi  = (unsigned)((lane >> 4) & 1);
    const unsigned brow_l = (unsigned)(wn + (lane & 7) + ((lane >> 4) & 1) * 8);
    const unsigned bhi  = (unsigned)((lane >> 3) & 1);

    float acc[4][4][4];
#pragma unroll
    for (int i = 0; i < 4; i++)
#pragma unroll
        for (int j = 0; j < 4; j++)
#pragma unroll
            for (int c = 0; c < 4; c++) acc[i][j][c] = 0.f;

    const int niter = K / 64;
    LOAD_STAGE(0, 0); CP_COMMIT();
    LOAD_STAGE(1, 1); CP_COMMIT();

    for (int it = 0; it < niter; it++) {
        CP_WAIT1();
        __syncthreads();
        const unsigned sb = sbase + (unsigned)(it & 1) * STAGE_B;

#pragma unroll
        for (int ks = 0; ks < 64; ks += 16) {
            const unsigned c16a = (unsigned)(ks >> 3) + ahi;   // 16B col index
            const unsigned c16b = (unsigned)(ks >> 3) + bhi;
            unsigned ah[4][4], al[4][4], bh[4][2], bl[4][2];
#pragma unroll
            for (int i = 0; i < 4; i++) {
                unsigned ra = arow + (unsigned)(i * 16);
                unsigned ad = sb + ra * 128u + ((c16a ^ (ra & 7u)) << 4);
                LDSM_X4(ah[i][0], ah[i][1], ah[i][2], ah[i][3], ad);
                LDSM_X4(al[i][0], al[i][1], al[i][2], al[i][3], ad + ARR_BYTES);
            }
#pragma unroll
            for (int jp = 0; jp < 2; jp++) {
                unsigned rb = brow_l + (unsigned)(jp * 16);
                unsigned bd = sb + 2 * ARR_BYTES + rb * 128u + ((c16b ^ (rb & 7u)) << 4);
                LDSM_X4(bh[2 * jp][0], bh[2 * jp][1], bh[2 * jp + 1][0], bh[2 * jp + 1][1], bd);
                LDSM_X4(bl[2 * jp][0], bl[2 * jp][1], bl[2 * jp + 1][0], bl[2 * jp + 1][1], bd + ARR_BYTES);
            }
#pragma unroll
            for (int i = 0; i < 4; i++)
#pragma unroll
                for (int j = 0; j < 4; j++) {
                    float* c = acc[i][j];
                    MMA_BF16(c, ah[i][0], ah[i][1], ah[i][2], ah[i][3], bh[j][0], bh[j][1]);
                    MMA_BF16(c, ah[i][0], ah[i][1], ah[i][2], ah[i][3], bl[j][0], bl[j][1]);
                    MMA_BF16(c, al[i][0], al[i][1], al[i][2], al[i][3], bh[j][0], bh[j][1]);
                }
        }
        __syncthreads();
        if (it + 2 < niter) LOAD_STAGE(it & 1, it + 2);
        CP_COMMIT();
    }
#undef LOAD_STAGE

#pragma unroll
    for (int i = 0; i < 4; i++) {
        const int r0 = brow + wm + i * 16 + g;
#pragma unroll
        for (int j = 0; j < 4; j++) {
            const int cc = ccol + wn + j * 8 + 2 * t;
            *(float2*)(C + (size_t)r0 * ldc + cc)       = make_float2(acc[i][j][0], acc[i][j][1]);
            *(float2*)(C + (size_t)(r0 + 8) * ldc + cc) = make_float2(acc[i][j][2], acc[i][j][3]);
        }
    }
}

// ---------------------------------------------------------------------------
// Tensor-core flash attention (validated R6/R8, unchanged)
// ---------------------------------------------------------------------------
#define KROW 136
#define VROW 72

__global__ __launch_bounds__(256) void flash_mma_kernel(
    const __nv_bfloat16* __restrict__ Qh, const __nv_bfloat16* __restrict__ Ql,
    const __nv_bfloat16* __restrict__ Kh, const __nv_bfloat16* __restrict__ Kl,
    const __nv_bfloat16* __restrict__ Vth, const __nv_bfloat16* __restrict__ Vtl,
    float* __restrict__ O)
{
    extern __shared__ __nv_bfloat16 smem_bf[];
    __nv_bfloat16* kh = smem_bf;
    __nv_bfloat16* kl = kh + 64 * KROW;
    __nv_bfloat16* vh = kl + 64 * KROW;
    __nv_bfloat16* vl = vh + 128 * VROW;

    const int qb  = (int)gridDim.x - 1 - (int)blockIdx.x;
    const int bh  = blockIdx.y;
    const int b   = bh >> 4;
    const int h   = bh & 15;
    const int kvh = h >> 2;

    const int tid  = threadIdx.x;
    const int lane = tid & 31;
    const int w    = tid >> 5;
    const int g    = lane >> 2;
    const int t    = lane & 3;
    const int m0   = w * 16;

    unsigned qfh[8][4], qfl[8][4];
    {
        const __nv_bfloat16* Qb  = Qh + ((size_t)(b * S_ + qb * 128 + m0)) * H_ + h * HD;
        const __nv_bfloat16* Qlb = Ql + ((size_t)(b * S_ + qb * 128 + m0)) * H_ + h * HD;
#pragma unroll
        for (int kc = 0; kc < 8; kc++) {
            int c0 = kc * 16 + 2 * t;
            qfh[kc][0] = *(const unsigned*)(Qb  + (size_t)g * H_ + c0);
            qfh[kc][1] = *(const unsigned*)(Qb  + (size_t)(g + 8) * H_ + c0);
            qfh[kc][2] = *(const unsigned*)(Qb  + (size_t)g * H_ + c0 + 8);
            qfh[kc][3] = *(const unsigned*)(Qb  + (size_t)(g + 8) * H_ + c0 + 8);
            qfl[kc][0] = *(const unsigned*)(Qlb + (size_t)g * H_ + c0);
            qfl[kc][1] = *(const unsigned*)(Qlb + (size_t)(g + 8) * H_ + c0);
            qfl[kc][2] = *(const unsigned*)(Qlb + (size_t)g * H_ + c0 + 8);
            qfl[kc][3] = *(const unsigned*)(Qlb + (size_t)(g + 8) * H_ + c0 + 8);
        }
    }

    float oacc[16][4];
#pragma unroll
    for (int jn = 0; jn < 16; jn++)
#pragma unroll
        for (int c = 0; c < 4; c++) oacc[jn][c] = 0.f;
    float mrow0 = -INFINITY, mrow1 = -INFINITY;
    float lrow0 = 0.f, lrow1 = 0.f;

    const float scale = 0.08838834764831845f;
    const int njt = 2 * qb + 2;

    for (int j = 0; j < njt; j++) {
        __syncthreads();
        {
            const __nv_bfloat16* Kb  = Kh + (size_t)(b * S_ + j * 64) * KV_DIM + kvh * HD;
            const __nv_bfloat16* Klb = Kl + (size_t)(b * S_ + j * 64) * KV_DIM + kvh * HD;
#pragma unroll
            for (int it = 0; it < 4; it++) {
                int idx = tid + it * 256;
                int r  = idx >> 4;
                int c8 = (idx & 15) * 8;
                *(uint4*)&kh[r * KROW + c8] = *(const uint4*)(Kb  + (size_t)r * KV_DIM + c8);
                *(uint4*)&kl[r * KROW + c8] = *(const uint4*)(Klb + (size_t)r * KV_DIM + c8);
            }
            const __nv_bfloat16* Vb  = Vth + ((size_t)((b * NKV + kvh) * HD)) * S_ + j * 64;
            const __nv_bfloat16* Vlb = Vtl + ((size_t)((b * NKV + kvh) * HD)) * S_ + j * 64;
#pragma unroll
            for (int it = 0; it < 4; it++) {
                int idx = tid + it * 256;
                int r  = idx >> 3;
                int c8 = (idx & 7) * 8;
                *(uint4*)&vh[r * VROW + c8] = *(const uint4*)(Vb  + (size_t)r * S_ + c8);
                *(uint4*)&vl[r * VROW + c8] = *(const uint4*)(Vlb + (size_t)r * S_ + c8);
            }
        }
        __syncthreads();

        float sf[8][4];
#pragma unroll
        for (int jn = 0; jn < 8; jn++)
#pragma unroll
            for (int c = 0; c < 4; c++) sf[jn][c] = 0.f;

#pragma unroll
        for (int jn = 0; jn < 8; jn++) {
            const int n0 = jn * 8;
#pragma unroll
            for (int kc = 0; kc < 8; kc++) {
                const int ck = kc * 16 + 2 * t;
                unsigned b0h = *(const unsigned*)&kh[(n0 + g) * KROW + ck];
                unsigned b1h = *(const unsigned*)&kh[(n0 + g) * KROW + ck + 8];
                unsigned b0l = *(const unsigned*)&kl[(n0 + g) * KROW + ck];
                unsigned b1l = *(const unsigned*)&kl[(n0 + g) * KROW + ck + 8];
                float* c = sf[jn];
                MMA_BF16(c, qfh[kc][0], qfh[kc][1], qfh[kc][2], qfh[kc][3], b0h, b1h);
                MMA_BF16(c, qfh[kc][0], qfh[kc][1], qfh[kc][2], qfh[kc][3], b0l, b1l);
                MMA_BF16(c, qfl[kc][0], qfl[kc][1], qfl[kc][2], qfl[kc][3], b0h, b1h);
            }
        }

        const int row0 = qb * 128 + m0 + g;
        const int row1 = row0 + 8;
        const bool need_mask = (j >= 2 * qb);
#pragma unroll
        for (int jn = 0; jn < 8; jn++) {
            const int cbase = j * 64 + jn * 8 + 2 * t;
#pragma unroll
            for (int c = 0; c < 4; c++) sf[jn][c] *= scale;
            if (need_mask) {
                if (cbase     > row0) sf[jn][0] = -1e30f;
                if (cbase + 1 > row0) sf[jn][1] = -1e30f;
                if (cbase     > row1) sf[jn][2] = -1e30f;
                if (cbase + 1 > row1) sf[jn][3] = -1e30f;
            }
        }

        float mx0 = -INFINITY, mx1 = -INFINITY;
#pragma unroll
        for (int jn = 0; jn < 8; jn++) {
            mx0 = fmaxf(mx0, fmaxf(sf[jn][0], sf[jn][1]));
            mx1 = fmaxf(mx1, fmaxf(sf[jn][2], sf[jn][3]));
        }
        mx0 = fmaxf(mx0, __shfl_xor_sync(0xffffffffu, mx0, 1));
        mx0 = fmaxf(mx0, __shfl_xor_sync(0xffffffffu, mx0, 2));
        mx1 = fmaxf(mx1, __shfl_xor_sync(0xffffffffu, mx1, 1));
        mx1 = fmaxf(mx1, __shfl_xor_sync(0xffffffffu, mx1, 2));
        float mn0 = fmaxf(mrow0, mx0);
        float mn1 = fmaxf(mrow1, mx1);
        float f0 = __expf(mrow0 - mn0);
        float f1 = __expf(mrow1 - mn1);
        mrow0 = mn0; mrow1 = mn1;

        float sum0 = 0.f, sum1 = 0.f;
#pragma unroll
        for (int jn = 0; jn < 8; jn++) {
            sf[jn][0] = __expf(sf[jn][0] - mn0);
            sf[jn][1] = __expf(sf[jn][1] - mn0);
            sf[jn][2] = __expf(sf[jn][2] - mn1);
            sf[jn][3] = __expf(sf[jn][3] - mn1);
            sum0 += sf[jn][0] + sf[jn][1];
            sum1 += sf[jn][2] + sf[jn][3];
        }
        sum0 += __shfl_xor_sync(0xffffffffu, sum0, 1);
        sum0 += __shfl_xor_sync(0xffffffffu, sum0, 2);
        sum1 += __shfl_xor_sync(0xffffffffu, sum1, 1);
        sum1 += __shfl_xor_sync(0xffffffffu, sum1, 2);
        lrow0 = lrow0 * f0 + sum0;
        lrow1 = lrow1 * f1 + sum1;

#pragma unroll
        for (int jn = 0; jn < 16; jn++) {
            oacc[jn][0] *= f0; oacc[jn][1] *= f0;
            oacc[jn][2] *= f1; oacc[jn][3] *= f1;
        }

#pragma unroll
        for (int kc = 0; kc < 4; kc++) {
            const int j0 = 2 * kc, j1 = 2 * kc + 1;
            unsigned a0h = pack_bf16(sf[j0][0], sf[j0][1]);
            unsigned a1h = pack_bf16(sf[j0][2], sf[j0][3]);
            unsigned a2h = pack_bf16(sf[j1][0], sf[j1][1]);
            unsigned a3h = pack_bf16(sf[j1][2], sf[j1][3]);
            unsigned a0l = pack_bf16(sf[j0][0] - __uint_as_float(a0h << 16),
                                     sf[j0][1] - __uint_as_float(a0h & 0xffff0000u));
            unsigned a1l = pack_bf16(sf[j0][2] - __uint_as_float(a1h << 16),
                                     sf[j0][3] - __uint_as_float(a1h & 0xffff0000u));
            unsigned a2l = pack_bf16(sf[j1][0] - __uint_as_float(a2h << 16),
                                     sf[j1][1] - __uint_as_float(a2h & 0xffff0000u));
            unsigned a3l = pack_bf16(sf[j1][2] - __uint_as_float(a3h << 16),
                                     sf[j1][3] - __uint_as_float(a3h & 0xffff0000u));
            const int ck = kc * 16 + 2 * t;
#pragma unroll
            for (int jn = 0; jn < 16; jn++) {
                const int n0 = jn * 8;
                unsigned b0h = *(const unsigned*)&vh[(n0 + g) * VROW + ck];
                unsigned b1h = *(const unsigned*)&vh[(n0 + g) * VROW + ck + 8];
                unsigned b0l = *(const unsigned*)&vl[(n0 + g) * VROW + ck];
                unsigned b1l = *(const unsigned*)&vl[(n0 + g) * VROW + ck + 8];
                float* c = oacc[jn];
                MMA_BF16(c, a0h, a1h, a2h, a3h, b0h, b1h);
                MMA_BF16(c, a0h, a1h, a2h, a3h, b0l, b1l);
                MMA_BF16(c, a0l, a1l, a2l, a3l, b0h, b1h);
            }
        }
    }

    {
        float inv0 = 1.f / lrow0;
        float inv1 = 1.f / lrow1;
        float* Ob = O + ((size_t)(b * S_ + qb * 128 + m0 + g)) * H_ + h * HD;
#pragma unroll
        for (int jn = 0; jn < 16; jn++) {
            const int cc = jn * 8 + 2 * t;
            *(float2*)(Ob + cc)          = make_float2(oacc[jn][0] * inv0, oacc[jn][1] * inv0);
            *(float2*)(Ob + 8 * H_ + cc) = make_float2(oacc[jn][2] * inv1, oacc[jn][3] * inv1);
        }
    }
}

// ---------------------------------------------------------------------------
extern "C" void kernel_launch(void* const* d_in, const int* in_sizes, int n_in,
                              void* d_out, int out_size)
{
    const float* x  = (const float*)d_in[0];
    const float* rc = (const float*)d_in[1];
    const float* rs = (const float*)d_in[2];
    const float* wq = (const float*)d_in[4];
    const float* wk = (const float*)d_in[5];
    const float* wv = (const float*)d_in[6];
    const float* wo = (const float*)d_in[7];
    float* out = (float*)d_out;

    float *Q, *K, *V, *AO;
    cudaGetSymbolAddress((void**)&Q,  g_Q);
    cudaGetSymbolAddress((void**)&K,  g_K);
    cudaGetSymbolAddress((void**)&V,  g_V);
    cudaGetSymbolAddress((void**)&AO, g_AO);

    __nv_bfloat16 *xh, *xl, *aoh, *aol;
    __nv_bfloat16 *qh, *ql, *kh, *kl, *vth, *vtl;
    __nv_bfloat16 *wqkvh, *wqkvl, *woh, *wol;
    cudaGetSymbolAddress((void**)&xh,  g_xh);
    cudaGetSymbolAddress((void**)&xl,  g_xl);
    cudaGetSymbolAddress((void**)&aoh, g_aoh);
    cudaGetSymbolAddress((void**)&aol, g_aol);
    cudaGetSymbolAddress((void**)&qh,  g_Qh);
    cudaGetSymbolAddress((void**)&ql,  g_Ql);
    cudaGetSymbolAddress((void**)&kh,  g_Kh);
    cudaGetSymbolAddress((void**)&kl,  g_Kl);
    cudaGetSymbolAddress((void**)&vth, g_Vth);
    cudaGetSymbolAddress((void**)&vtl, g_Vtl);
    cudaGetSymbolAddress((void**)&wqkvh, g_wqkvh);
    cudaGetSymbolAddress((void**)&wqkvl, g_wqkvl);
    cudaGetSymbolAddress((void**)&woh, g_woh);
    cudaGetSymbolAddress((void**)&wol, g_wol);

    // Prep: tiled-K transpose+split weights, tiled split x
    dim3 tsb(32, 8);
    tsplit_tiled_kernel<<<dim3(H_ / 32,     H_ / 32), tsb>>>(wq, wqkvh, wqkvl, H_,     0,            NQKV);
    tsplit_tiled_kernel<<<dim3(KV_DIM / 32, H_ / 32), tsb>>>(wk, wqkvh, wqkvl, KV_DIM, H_,           NQKV);
    tsplit_tiled_kernel<<<dim3(KV_DIM / 32, H_ / 32), tsb>>>(wv, wqkvh, wqkvl, KV_DIM, H_ + KV_DIM,  NQKV);
    tsplit_tiled_kernel<<<dim3(H_ / 32,     H_ / 32), tsb>>>(wo, woh,   wol,   H_,     0,            H_);
    split_tiled_kernel<<<(M_ * H_ + 255) / 256, 256>>>(x, xh, xl, M_);

    // Fused QKV projection
    const int gemm_smem = 2 * (int)STAGE_B;   // 128 KB
    cudaFuncSetAttribute(bf16x3_gemm_tiled,
                         cudaFuncAttributeMaxDynamicSharedMemorySize, gemm_smem);
    bf16x3_gemm_tiled<<<dim3(NQKV / 128, M_ / 128), 256, gemm_smem>>>(
        xh, xl, wqkvh, wqkvl, Q, K, V,
        H_ / 128, KV_DIM / 128, H_, KV_DIM, KV_DIM, H_, M_, NQKV);

    // RoPE + split; V split + transpose
    {
        int nq = M_ * NH  * 64;
        int nk = M_ * NKV * 64;
        rope_split_kernel<<<(nq + 255) / 256, 256>>>(Q, rc, rs, NH,  qh, ql);
        rope_split_kernel<<<(nk + 255) / 256, 256>>>(K, rc, rs, NKV, kh, kl);
        vsplit_t_kernel<<<dim3(S_ / 32, HD / 32, B_ * NKV), tsb>>>(V, vth, vtl);
    }

    // Flash attention (mma.sync)
    {
        size_t shmem = (size_t)(2 * 64 * KROW + 2 * 128 * VROW) * sizeof(__nv_bfloat16);
        cudaFuncSetAttribute(flash_mma_kernel,
                             cudaFuncAttributeMaxDynamicSharedMemorySize,
                             (int)shmem);
        flash_mma_kernel<<<dim3(S_ / 128, B_ * NH), 256, shmem>>>(qh, ql, kh, kl, vth, vtl, AO);
    }

    // Output projection
    split_tiled_kernel<<<(M_ * H_ + 255) / 256, 256>>>(AO, aoh, aol, M_);
    bf16x3_gemm_tiled<<<dim3(H_ / 128, M_ / 128), 256, gemm_smem>>>(
        aoh, aol, woh, wol, out, out, out,
        H_ / 128, 0, H_, H_, H_, H_, M_, H_);
}

// round 11
// speedup vs baseline: 1.2435x; 1.0374x over previous
#include <cuda_runtime.h>
#include <cuda_bf16.h>
#include <math.h>
#include <stdint.h>

#define B_  2
#define S_  2048
#define H_  2048
#define NH  16
#define NKV 4
#define HD  128
#define KV_DIM (NKV*HD)   // 512
#define M_  (B_*S_)       // 4096
#define NQKV (H_ + 2*KV_DIM)  // 3072

// fp32 scratch
__device__ float g_Q[M_ * H_];
__device__ float g_K[M_ * KV_DIM];
__device__ float g_V[M_ * KV_DIM];

// bf16 split operands. GEMM operands use tiled-K layout [K/64][rows][64].
__device__ __nv_bfloat16 g_xh[M_ * H_],  g_xl[M_ * H_];          // tiled, rows=M_
__device__ __nv_bfloat16 g_aoh[M_ * H_], g_aol[M_ * H_];         // tiled, rows=M_ (written by flash)
__device__ __nv_bfloat16 g_wqkvh[NQKV * H_], g_wqkvl[NQKV * H_]; // tiled, rows=NQKV
__device__ __nv_bfloat16 g_woh[H_ * H_],     g_wol[H_ * H_];     // tiled, rows=H_
// flash operands (row-major)
__device__ __nv_bfloat16 g_Qh[M_ * H_],     g_Ql[M_ * H_];
__device__ __nv_bfloat16 g_Kh[M_ * KV_DIM], g_Kl[M_ * KV_DIM];
__device__ __nv_bfloat16 g_Vth[M_ * KV_DIM], g_Vtl[M_ * KV_DIM];

__device__ __forceinline__ unsigned pack_bf16(float lo, float hi) {
    unsigned d;
    asm("cvt.rn.bf16x2.f32 %0, %1, %2;" : "=r"(d) : "f"(hi), "f"(lo));
    return d;
}
__device__ __forceinline__ unsigned smem_u32(const void* p) {
    return (unsigned)__cvta_generic_to_shared(p);
}

#define LDSM_X4(r0, r1, r2, r3, addr) \
    asm volatile("ldmatrix.sync.aligned.m8n8.x4.shared.b16 {%0,%1,%2,%3}, [%4];" \
        : "=r"(r0), "=r"(r1), "=r"(r2), "=r"(r3) : "r"(addr))

#define CP_ASYNC16(dst, src) \
    asm volatile("cp.async.cg.shared.global [%0], [%1], 16;" :: "r"(dst), "l"(src) : "memory")
#define CP_COMMIT()  asm volatile("cp.async.commit_group;" ::: "memory")
#define CP_WAIT1()   asm volatile("cp.async.wait_group 1;" ::: "memory")

#define MMA_BF16(c, a0,a1,a2,a3, b0,b1) \
    asm volatile( \
        "mma.sync.aligned.m16n8k16.row.col.f32.bf16.bf16.f32 " \
        "{%0,%1,%2,%3}, {%4,%5,%6,%7}, {%8,%9}, {%0,%1,%2,%3};" \
        : "+f"((c)[0]), "+f"((c)[1]), "+f"((c)[2]), "+f"((c)[3]) \
        : "r"(a0), "r"(a1), "r"(a2), "r"(a3), "r"(b0), "r"(b1))

// ---------------------------------------------------------------------------
// Split x into tiled-K layout [K/64][rows][64]
// ---------------------------------------------------------------------------
__global__ void split_tiled_kernel(const float* __restrict__ in,
                                   __nv_bfloat16* __restrict__ hi,
                                   __nv_bfloat16* __restrict__ lo, int rows)
{
    int i = blockIdx.x * blockDim.x + threadIdx.x;
    if (i >= rows * H_) return;
    int row = i >> 11;
    int k   = i & 2047;
    float x = in[i];
    __nv_bfloat16 h = __float2bfloat16(x);
    size_t o = (size_t)(k >> 6) * rows * 64 + (size_t)row * 64 + (k & 63);
    hi[o] = h;
    lo[o] = __float2bfloat16(x - __bfloat162float(h));
}

// ---------------------------------------------------------------------------
// Transpose + split: W[K][N] fp32 -> tiled [k/64][n_total][64] at n_base
// ---------------------------------------------------------------------------
__global__ void tsplit_tiled_kernel(const float* __restrict__ W,
                                    __nv_bfloat16* __restrict__ Th,
                                    __nv_bfloat16* __restrict__ Tl,
                                    int N, int n_base, int n_total)
{
    __shared__ float tile[32][33];
    const int n0 = blockIdx.x * 32;
    const int k0 = blockIdx.y * 32;
    const int tx = threadIdx.x, ty = threadIdx.y;
#pragma unroll
    for (int r = 0; r < 32; r += 8)
        tile[ty + r][tx] = W[(size_t)(k0 + ty + r) * N + n0 + tx];
    __syncthreads();
#pragma unroll
    for (int r = 0; r < 32; r += 8) {
        float v = tile[tx][ty + r];
        __nv_bfloat16 h = __float2bfloat16(v);
        int k = k0 + tx;
        int n = n_base + n0 + ty + r;
        size_t o = (size_t)(k >> 6) * n_total * 64 + (size_t)n * 64 + (k & 63);
        Th[o] = h;
        Tl[o] = __float2bfloat16(v - __bfloat162float(h));
    }
}

// ---------------------------------------------------------------------------
// RoPE + split (row-major output, for flash)
// ---------------------------------------------------------------------------
__global__ void rope_split_kernel(const float* __restrict__ buf,
                                  const float* __restrict__ ct,
                                  const float* __restrict__ st,
                                  int nheads,
                                  __nv_bfloat16* __restrict__ hi,
                                  __nv_bfloat16* __restrict__ lo)
{
    int i = blockIdx.x * blockDim.x + threadIdx.x;
    int total = M_ * nheads * 64;
    if (i >= total) return;
    int d   = i & 63;
    int h   = (i >> 6) % nheads;
    int row = i / (64 * nheads);
    int s   = row & (S_ - 1);
    float c  = ct[s * 64 + d];
    float sn = st[s * 64 + d];
    size_t o = (size_t)row * (nheads * HD) + h * HD + d;
    float x1 = buf[o], x2 = buf[o + 64];
    float y1 = x1 * c - x2 * sn;
    float y2 = x2 * c + x1 * sn;
    __nv_bfloat16 h1 = __float2bfloat16(y1);
    __nv_bfloat16 h2 = __float2bfloat16(y2);
    hi[o]      = h1;
    hi[o + 64] = h2;
    lo[o]      = __float2bfloat16(y1 - __bfloat162float(h1));
    lo[o + 64] = __float2bfloat16(y2 - __bfloat162float(h2));
}

// ---------------------------------------------------------------------------
// V split + transpose (for flash)
// ---------------------------------------------------------------------------
__global__ void vsplit_t_kernel(const float* __restrict__ V,
                                __nv_bfloat16* __restrict__ Th,
                                __nv_bfloat16* __restrict__ Tl)
{
    __shared__ float tile[32][33];
    const int s0 = blockIdx.x * 32;
    const int d0 = blockIdx.y * 32;
    const int bk = blockIdx.z;
    const int b  = bk / NKV;
    const int kvh = bk % NKV;
    const int tx = threadIdx.x, ty = threadIdx.y;
#pragma unroll
    for (int r = 0; r < 32; r += 8)
        tile[ty + r][tx] = V[(size_t)(b * S_ + s0 + ty + r) * KV_DIM + kvh * HD + d0 + tx];
    __syncthreads();
#pragma unroll
    for (int r = 0; r < 32; r += 8) {
        float v = tile[tx][ty + r];
        __nv_bfloat16 h = __float2bfloat16(v);
        size_t o = (size_t)(bk * HD + d0 + ty + r) * S_ + s0 + tx;
        Th[o] = h;
        Tl[o] = __float2bfloat16(v - __bfloat162float(h));
    }
}

// ---------------------------------------------------------------------------
// bf16x3 GEMM, 256x128 CTA tile, tiled-K operands, BK=64, cp.async 2-stage.
// 8 warps (4x2), each 64x64. Smem XOR-16B swizzle, coalesced loads.
// ---------------------------------------------------------------------------
#define A_BYTES  32768u               // 256 rows * 128 B
#define BB_BYTES 16384u               // 128 rows * 128 B
#define STAGE_B  (2u * A_BYTES + 2u * BB_BYTES)   // 98304

__global__ __launch_bounds__(256) void bf16x3_gemm_tiled(
    const __nv_bfloat16* __restrict__ Ah, const __nv_bfloat16* __restrict__ Al,
    const __nv_bfloat16* __restrict__ Bh, const __nv_bfloat16* __restrict__ Bl,
    float* __restrict__ C0, float* __restrict__ C1, float* __restrict__ C2,
    int t0, int t1, int ldc0, int ldc1, int ldc2, int K, int An, int Bn)
{
    extern __shared__ unsigned char smem_raw[];
    const unsigned sbase = smem_u32(smem_raw);

    const int tid  = threadIdx.x;
    const int lane = tid & 31;
    const int warp = tid >> 5;
    const int g = lane >> 2;
    const int t = lane & 3;
    const int wm = (warp & 3) * 64;    // 4 m-slots
    const int wn = (warp >> 2) * 64;   // 2 n-slots

    const int bx   = blockIdx.x;
    const int brow = blockIdx.y * 256;
    const int bcolB = bx * 128;

    float* C; int ldc; int ccol;
    if (bx < t0)           { C = C0; ldc = ldc0; ccol = bx * 128; }
    else if (bx < t0 + t1) { C = C1; ldc = ldc1; ccol = (bx - t0) * 128; }
    else                   { C = C2; ldc = ldc2; ccol = (bx - t0 - t1) * 128; }

    const size_t aStride = (size_t)An * 64;
    const size_t bStride = (size_t)Bn * 64;
    const __nv_bfloat16* aBaseH = Ah + (size_t)brow * 64;
    const __nv_bfloat16* aBaseL = Al + (size_t)brow * 64;
    const __nv_bfloat16* bBaseH = Bh + (size_t)bcolB * 64;
    const __nv_bfloat16* bBaseL = Bl + (size_t)bcolB * 64;

#define LOAD_STAGE(s, ch) do {                                                       \
    const unsigned sb = sbase + (unsigned)(s) * STAGE_B;                             \
    const size_t aoffg = (size_t)(ch) * aStride;                                     \
    const size_t boffg = (size_t)(ch) * bStride;                                     \
    _Pragma("unroll")                                                                \
    for (int i_ = 0; i_ < 8; i_++) {     /* A: 2048 units per array */               \
        int u  = tid + i_ * 256;                                                     \
        int r_ = u >> 3;                                                             \
        int c8 = u & 7;                                                              \
        unsigned d_ = (unsigned)(r_ * 128 + (((unsigned)c8 ^ ((unsigned)r_ & 7u)) << 4)); \
        size_t gsrc = (size_t)r_ * 64 + (size_t)c8 * 8;                              \
        CP_ASYNC16(sb + d_,           aBaseH + aoffg + gsrc);                        \
        CP_ASYNC16(sb + A_BYTES + d_, aBaseL + aoffg + gsrc);                        \
    }                                                                                \
    _Pragma("unroll")                                                                \
    for (int i_ = 0; i_ < 4; i_++) {     /* B: 1024 units per array */               \
        int u  = tid + i_ * 256;                                                     \
        int r_ = u >> 3;                                                             \
        int c8 = u & 7;                                                              \
        unsigned d_ = (unsigned)(r_ * 128 + (((unsigned)c8 ^ ((unsigned)r_ & 7u)) << 4)); \
        size_t gsrc = (size_t)r_ * 64 + (size_t)c8 * 8;                              \
        CP_ASYNC16(sb + 2 * A_BYTES + d_,            bBaseH + boffg + gsrc);         \
        CP_ASYNC16(sb + 2 * A_BYTES + BB_BYTES + d_, bBaseL + boffg + gsrc);         \
    }                                                                                \
} while (0)

    const unsigned arow   = (unsigned)(wm + (lane & 7) + ((lane >> 3) & 1) * 8);
    const unsigned ahi    = (unsigned)((lane >> 4) & 1);
    const unsigned brow_l = (unsigned)(wn + (lane & 7) + ((lane >> 4) & 1) * 8);
    const unsigned bhi    = (unsigned)((lane >> 3) & 1);

    float acc[4][8][4];
#pragma unroll
    for (int i = 0; i < 4; i++)
#pragma unroll
        for (int j = 0; j < 8; j++)
#pragma unroll
            for (int c = 0; c < 4; c++) acc[i][j][c] = 0.f;

    const int niter = K / 64;
    LOAD_STAGE(0, 0); CP_COMMIT();
    LOAD_STAGE(1, 1); CP_COMMIT();

    for (int it = 0; it < niter; it++) {
        CP_WAIT1();
        __syncthreads();
        const unsigned sb = sbase + (unsigned)(it & 1) * STAGE_B;

#pragma unroll
        for (int ks = 0; ks < 64; ks += 16) {
            const unsigned c16a = (unsigned)(ks >> 3) + ahi;
            const unsigned c16b = (unsigned)(ks >> 3) + bhi;
            unsigned ah[4][4], al[4][4], bh[8][2], bl[8][2];
#pragma unroll
            for (int i = 0; i < 4; i++) {
                unsigned ra = arow + (unsigned)(i * 16);
                unsigned ad = sb + ra * 128u + ((c16a ^ (ra & 7u)) << 4);
                LDSM_X4(ah[i][0], ah[i][1], ah[i][2], ah[i][3], ad);
                LDSM_X4(al[i][0], al[i][1], al[i][2], al[i][3], ad + A_BYTES);
            }
#pragma unroll
            for (int jp = 0; jp < 4; jp++) {
                unsigned rb = brow_l + (unsigned)(jp * 16);
                unsigned bd = sb + 2 * A_BYTES + rb * 128u + ((c16b ^ (rb & 7u)) << 4);
                LDSM_X4(bh[2 * jp][0], bh[2 * jp][1], bh[2 * jp + 1][0], bh[2 * jp + 1][1], bd);
                LDSM_X4(bl[2 * jp][0], bl[2 * jp][1], bl[2 * jp + 1][0], bl[2 * jp + 1][1], bd + BB_BYTES);
            }
#pragma unroll
            for (int i = 0; i < 4; i++)
#pragma unroll
                for (int j = 0; j < 8; j++) {
                    float* c = acc[i][j];
                    MMA_BF16(c, ah[i][0], ah[i][1], ah[i][2], ah[i][3], bh[j][0], bh[j][1]);
                    MMA_BF16(c, ah[i][0], ah[i][1], ah[i][2], ah[i][3], bl[j][0], bl[j][1]);
                    MMA_BF16(c, al[i][0], al[i][1], al[i][2], al[i][3], bh[j][0], bh[j][1]);
                }
        }
        __syncthreads();
        if (it + 2 < niter) LOAD_STAGE(it & 1, it + 2);
        CP_COMMIT();
    }
#undef LOAD_STAGE

#pragma unroll
    for (int i = 0; i < 4; i++) {
        const int r0 = brow + wm + i * 16 + g;
#pragma unroll
        for (int j = 0; j < 8; j++) {
            const int cc = ccol + wn + j * 8 + 2 * t;
            *(float2*)(C + (size_t)r0 * ldc + cc)       = make_float2(acc[i][j][0], acc[i][j][1]);
            *(float2*)(C + (size_t)(r0 + 8) * ldc + cc) = make_float2(acc[i][j][2], acc[i][j][3]);
        }
    }
}

// ---------------------------------------------------------------------------
// Tensor-core flash attention. Epilogue writes split bf16 directly in
// tiled-K layout (feeds the WO GEMM) — no fp32 AO roundtrip.
// ---------------------------------------------------------------------------
#define KROW 136
#define VROW 72

__global__ __launch_bounds__(256) void flash_mma_kernel(
    const __nv_bfloat16* __restrict__ Qh, const __nv_bfloat16* __restrict__ Ql,
    const __nv_bfloat16* __restrict__ Kh, const __nv_bfloat16* __restrict__ Kl,
    const __nv_bfloat16* __restrict__ Vth, const __nv_bfloat16* __restrict__ Vtl,
    __nv_bfloat16* __restrict__ AOh, __nv_bfloat16* __restrict__ AOl)
{
    extern __shared__ __nv_bfloat16 smem_bf[];
    __nv_bfloat16* kh = smem_bf;
    __nv_bfloat16* kl = kh + 64 * KROW;
    __nv_bfloat16* vh = kl + 64 * KROW;
    __nv_bfloat16* vl = vh + 128 * VROW;

    const int qb  = (int)gridDim.x - 1 - (int)blockIdx.x;
    const int bh  = blockIdx.y;
    const int b   = bh >> 4;
    const int h   = bh & 15;
    const int kvh = h >> 2;

    const int tid  = threadIdx.x;
    const int lane = tid & 31;
    const int w    = tid >> 5;
    const int g    = lane >> 2;
    const int t    = lane & 3;
    const int m0   = w * 16;

    unsigned qfh[8][4], qfl[8][4];
    {
        const __nv_bfloat16* Qb  = Qh + ((size_t)(b * S_ + qb * 128 + m0)) * H_ + h * HD;
        const __nv_bfloat16* Qlb = Ql + ((size_t)(b * S_ + qb * 128 + m0)) * H_ + h * HD;
#pragma unroll
        for (int kc = 0; kc < 8; kc++) {
            int c0 = kc * 16 + 2 * t;
            qfh[kc][0] = *(const unsigned*)(Qb  + (size_t)g * H_ + c0);
            qfh[kc][1] = *(const unsigned*)(Qb  + (size_t)(g + 8) * H_ + c0);
            qfh[kc][2] = *(const unsigned*)(Qb  + (size_t)g * H_ + c0 + 8);
            qfh[kc][3] = *(const unsigned*)(Qb  + (size_t)(g + 8) * H_ + c0 + 8);
            qfl[kc][0] = *(const unsigned*)(Qlb + (size_t)g * H_ + c0);
            qfl[kc][1] = *(const unsigned*)(Qlb + (size_t)(g + 8) * H_ + c0);
            qfl[kc][2] = *(const unsigned*)(Qlb + (size_t)g * H_ + c0 + 8);
            qfl[kc][3] = *(const unsigned*)(Qlb + (size_t)(g + 8) * H_ + c0 + 8);
        }
    }

    float oacc[16][4];
#pragma unroll
    for (int jn = 0; jn < 16; jn++)
#pragma unroll
        for (int c = 0; c < 4; c++) oacc[jn][c] = 0.f;
    float mrow0 = -INFINITY, mrow1 = -INFINITY;
    float lrow0 = 0.f, lrow1 = 0.f;

    const float scale = 0.08838834764831845f;
    const int njt = 2 * qb + 2;

    for (int j = 0; j < njt; j++) {
        __syncthreads();
        {
            const __nv_bfloat16* Kb  = Kh + (size_t)(b * S_ + j * 64) * KV_DIM + kvh * HD;
            const __nv_bfloat16* Klb = Kl + (size_t)(b * S_ + j * 64) * KV_DIM + kvh * HD;
#pragma unroll
            for (int it = 0; it < 4; it++) {
                int idx = tid + it * 256;
                int r  = idx >> 4;
                int c8 = (idx & 15) * 8;
                *(uint4*)&kh[r * KROW + c8] = *(const uint4*)(Kb  + (size_t)r * KV_DIM + c8);
                *(uint4*)&kl[r * KROW + c8] = *(const uint4*)(Klb + (size_t)r * KV_DIM + c8);
            }
            const __nv_bfloat16* Vb  = Vth + ((size_t)((b * NKV + kvh) * HD)) * S_ + j * 64;
            const __nv_bfloat16* Vlb = Vtl + ((size_t)((b * NKV + kvh) * HD)) * S_ + j * 64;
#pragma unroll
            for (int it = 0; it < 4; it++) {
                int idx = tid + it * 256;
                int r  = idx >> 3;
                int c8 = (idx & 7) * 8;
                *(uint4*)&vh[r * VROW + c8] = *(const uint4*)(Vb  + (size_t)r * S_ + c8);
                *(uint4*)&vl[r * VROW + c8] = *(const uint4*)(Vlb + (size_t)r * S_ + c8);
            }
        }
        __syncthreads();

        float sf[8][4];
#pragma unroll
        for (int jn = 0; jn < 8; jn++)
#pragma unroll
            for (int c = 0; c < 4; c++) sf[jn][c] = 0.f;

#pragma unroll
        for (int jn = 0; jn < 8; jn++) {
            const int n0 = jn * 8;
#pragma unroll
            for (int kc = 0; kc < 8; kc++) {
                const int ck = kc * 16 + 2 * t;
                unsigned b0h = *(const unsigned*)&kh[(n0 + g) * KROW + ck];
                unsigned b1h = *(const unsigned*)&kh[(n0 + g) * KROW + ck + 8];
                unsigned b0l = *(const unsigned*)&kl[(n0 + g) * KROW + ck];
                unsigned b1l = *(const unsigned*)&kl[(n0 + g) * KROW + ck + 8];
                float* c = sf[jn];
                MMA_BF16(c, qfh[kc][0], qfh[kc][1], qfh[kc][2], qfh[kc][3], b0h, b1h);
                MMA_BF16(c, qfh[kc][0], qfh[kc][1], qfh[kc][2], qfh[kc][3], b0l, b1l);
                MMA_BF16(c, qfl[kc][0], qfl[kc][1], qfl[kc][2], qfl[kc][3], b0h, b1h);
            }
        }

        const int row0 = qb * 128 + m0 + g;
        const int row1 = row0 + 8;
        const bool need_mask = (j >= 2 * qb);
#pragma unroll
        for (int jn = 0; jn < 8; jn++) {
            const int cbase = j * 64 + jn * 8 + 2 * t;
#pragma unroll
            for (int c = 0; c < 4; c++) sf[jn][c] *= scale;
            if (need_mask) {
                if (cbase     > row0) sf[jn][0] = -1e30f;
                if (cbase + 1 > row0) sf[jn][1] = -1e30f;
                if (cbase     > row1) sf[jn][2] = -1e30f;
                if (cbase + 1 > row1) sf[jn][3] = -1e30f;
            }
        }

        float mx0 = -INFINITY, mx1 = -INFINITY;
#pragma unroll
        for (int jn = 0; jn < 8; jn++) {
            mx0 = fmaxf(mx0, fmaxf(sf[jn][0], sf[jn][1]));
            mx1 = fmaxf(mx1, fmaxf(sf[jn][2], sf[jn][3]));
        }
        mx0 = fmaxf(mx0, __shfl_xor_sync(0xffffffffu, mx0, 1));
        mx0 = fmaxf(mx0, __shfl_xor_sync(0xffffffffu, mx0, 2));
        mx1 = fmaxf(mx1, __shfl_xor_sync(0xffffffffu, mx1, 1));
        mx1 = fmaxf(mx1, __shfl_xor_sync(0xffffffffu, mx1, 2));
        float mn0 = fmaxf(mrow0, mx0);
        float mn1 = fmaxf(mrow1, mx1);
        float f0 = __expf(mrow0 - mn0);
        float f1 = __expf(mrow1 - mn1);
        mrow0 = mn0; mrow1 = mn1;

        float sum0 = 0.f, sum1 = 0.f;
#pragma unroll
        for (int jn = 0; jn < 8; jn++) {
            sf[jn][0] = __expf(sf[jn][0] - mn0);
            sf[jn][1] = __expf(sf[jn][1] - mn0);
            sf[jn][2] = __expf(sf[jn][2] - mn1);
            sf[jn][3] = __expf(sf[jn][3] - mn1);
            sum0 += sf[jn][0] + sf[jn][1];
            sum1 += sf[jn][2] + sf[jn][3];
        }
        sum0 += __shfl_xor_sync(0xffffffffu, sum0, 1);
        sum0 += __shfl_xor_sync(0xffffffffu, sum0, 2);
        sum1 += __shfl_xor_sync(0xffffffffu, sum1, 1);
        sum1 += __shfl_xor_sync(0xffffffffu, sum1, 2);
        lrow0 = lrow0 * f0 + sum0;
        lrow1 = lrow1 * f1 + sum1;

#pragma unroll
        for (int jn = 0; jn < 16; jn++) {
            oacc[jn][0] *= f0; oacc[jn][1] *= f0;
            oacc[jn][2] *= f1; oacc[jn][3] *= f1;
        }

#pragma unroll
        for (int kc = 0; kc < 4; kc++) {
            const int j0 = 2 * kc, j1 = 2 * kc + 1;
            unsigned a0h = pack_bf16(sf[j0][0], sf[j0][1]);
            unsigned a1h = pack_bf16(sf[j0][2], sf[j0][3]);
            unsigned a2h = pack_bf16(sf[j1][0], sf[j1][1]);
            unsigned a3h = pack_bf16(sf[j1][2], sf[j1][3]);
            unsigned a0l = pack_bf16(sf[j0][0] - __uint_as_float(a0h << 16),
                                     sf[j0][1] - __uint_as_float(a0h & 0xffff0000u));
            unsigned a1l = pack_bf16(sf[j0][2] - __uint_as_float(a1h << 16),
                                     sf[j0][3] - __uint_as_float(a1h & 0xffff0000u));
            unsigned a2l = pack_bf16(sf[j1][0] - __uint_as_float(a2h << 16),
                                     sf[j1][1] - __uint_as_float(a2h & 0xffff0000u));
            unsigned a3l = pack_bf16(sf[j1][2] - __uint_as_float(a3h << 16),
                                     sf[j1][3] - __uint_as_float(a3h & 0xffff0000u));
            const int ck = kc * 16 + 2 * t;
#pragma unroll
            for (int jn = 0; jn < 16; jn++) {
                const int n0 = jn * 8;
                unsigned b0h = *(const unsigned*)&vh[(n0 + g) * VROW + ck];
                unsigned b1h = *(const unsigned*)&vh[(n0 + g) * VROW + ck + 8];
                unsigned b0l = *(const unsigned*)&vl[(n0 + g) * VROW + ck];
                unsigned b1l = *(const unsigned*)&vl[(n0 + g) * VROW + ck + 8];
                float* c = oacc[jn];
                MMA_BF16(c, a0h, a1h, a2h, a3h, b0h, b1h);
                MMA_BF16(c, a0h, a1h, a2h, a3h, b0l, b1l);
                MMA_BF16(c, a0l, a1l, a2l, a3l, b0h, b1h);
            }
        }
    }

    // epilogue: split + write tiled-K bf16 (k = h*128 + jn*8 + 2t)
    {
        float inv0 = 1.f / lrow0;
        float inv1 = 1.f / lrow1;
        const int row0 = b * S_ + qb * 128 + m0 + g;
        const int row1 = row0 + 8;
#pragma unroll
        for (int jn = 0; jn < 16; jn++) {
            int kk = h * HD + jn * 8 + 2 * t;
            int ch = kk >> 6;
            int wi = kk & 63;
            size_t o0 = (size_t)ch * (M_ * 64) + (size_t)row0 * 64 + wi;
            size_t o1 = (size_t)ch * (M_ * 64) + (size_t)row1 * 64 + wi;
            float v0 = oacc[jn][0] * inv0, v1 = oacc[jn][1] * inv0;
            float v2 = oacc[jn][2] * inv1, v3 = oacc[jn][3] * inv1;
            unsigned h01 = pack_bf16(v0, v1);
            unsigned h23 = pack_bf16(v2, v3);
            unsigned l01 = pack_bf16(v0 - __uint_as_float(h01 << 16),
                                     v1 - __uint_as_float(h01 & 0xffff0000u));
            unsigned l23 = pack_bf16(v2 - __uint_as_float(h23 << 16),
                                     v3 - __uint_as_float(h23 & 0xffff0000u));
            *(unsigned*)(AOh + o0) = h01;
            *(unsigned*)(AOl + o0) = l01;
            *(unsigned*)(AOh + o1) = h23;
            *(unsigned*)(AOl + o1) = l23;
        }
    }
}

// ---------------------------------------------------------------------------
extern "C" void kernel_launch(void* const* d_in, const int* in_sizes, int n_in,
                              void* d_out, int out_size)
{
    const float* x  = (const float*)d_in[0];
    const float* rc = (const float*)d_in[1];
    const float* rs = (const float*)d_in[2];
    const float* wq = (const float*)d_in[4];
    const float* wk = (const float*)d_in[5];
    const float* wv = (const float*)d_in[6];
    const float* wo = (const float*)d_in[7];
    float* out = (float*)d_out;

    float *Q, *K, *V;
    cudaGetSymbolAddress((void**)&Q,  g_Q);
    cudaGetSymbolAddress((void**)&K,  g_K);
    cudaGetSymbolAddress((void**)&V,  g_V);

    __nv_bfloat16 *xh, *xl, *aoh, *aol;
    __nv_bfloat16 *qh, *ql, *kh, *kl, *vth, *vtl;
    __nv_bfloat16 *wqkvh, *wqkvl, *woh, *wol;
    cudaGetSymbolAddress((void**)&xh,  g_xh);
    cudaGetSymbolAddress((void**)&xl,  g_xl);
    cudaGetSymbolAddress((void**)&aoh, g_aoh);
    cudaGetSymbolAddress((void**)&aol, g_aol);
    cudaGetSymbolAddress((void**)&qh,  g_Qh);
    cudaGetSymbolAddress((void**)&ql,  g_Ql);
    cudaGetSymbolAddress((void**)&kh,  g_Kh);
    cudaGetSymbolAddress((void**)&kl,  g_Kl);
    cudaGetSymbolAddress((void**)&vth, g_Vth);
    cudaGetSymbolAddress((void**)&vtl, g_Vtl);
    cudaGetSymbolAddress((void**)&wqkvh, g_wqkvh);
    cudaGetSymbolAddress((void**)&wqkvl, g_wqkvl);
    cudaGetSymbolAddress((void**)&woh, g_woh);
    cudaGetSymbolAddress((void**)&wol, g_wol);

    // Prep
    dim3 tsb(32, 8);
    tsplit_tiled_kernel<<<dim3(H_ / 32,     H_ / 32), tsb>>>(wq, wqkvh, wqkvl, H_,     0,           NQKV);
    tsplit_tiled_kernel<<<dim3(KV_DIM / 32, H_ / 32), tsb>>>(wk, wqkvh, wqkvl, KV_DIM, H_,          NQKV);
    tsplit_tiled_kernel<<<dim3(KV_DIM / 32, H_ / 32), tsb>>>(wv, wqkvh, wqkvl, KV_DIM, H_ + KV_DIM, NQKV);
    tsplit_tiled_kernel<<<dim3(H_ / 32,     H_ / 32), tsb>>>(wo, woh,   wol,   H_,     0,           H_);
    split_tiled_kernel<<<(M_ * H_ + 255) / 256, 256>>>(x, xh, xl, M_);

    // Fused QKV projection (256x128 tiles)
    const int gemm_smem = 2 * (int)STAGE_B;   // 192 KB
    cudaFuncSetAttribute(bf16x3_gemm_tiled,
                         cudaFuncAttributeMaxDynamicSharedMemorySize, gemm_smem);
    bf16x3_gemm_tiled<<<dim3(NQKV / 128, M_ / 256), 256, gemm_smem>>>(
        xh, xl, wqkvh, wqkvl, Q, K, V,
        H_ / 128, KV_DIM / 128, H_, KV_DIM, KV_DIM, H_, M_, NQKV);

    // RoPE + split; V split + transpose
    {
        int nq = M_ * NH  * 64;
        int nk = M_ * NKV * 64;
        rope_split_kernel<<<(nq + 255) / 256, 256>>>(Q, rc, rs, NH,  qh, ql);
        rope_split_kernel<<<(nk + 255) / 256, 256>>>(K, rc, rs, NKV, kh, kl);
        vsplit_t_kernel<<<dim3(S_ / 32, HD / 32, B_ * NKV), tsb>>>(V, vth, vtl);
    }

    // Flash attention (writes tiled split bf16 AO)
    {
        size_t shmem = (size_t)(2 * 64 * KROW + 2 * 128 * VROW) * sizeof(__nv_bfloat16);
        cudaFuncSetAttribute(flash_mma_kernel,
                             cudaFuncAttributeMaxDynamicSharedMemorySize,
                             (int)shmem);
        flash_mma_kernel<<<dim3(S_ / 128, B_ * NH), 256, shmem>>>(qh, ql, kh, kl, vth, vtl, aoh, aol);
    }

    // Output projection
    bf16x3_gemm_tiled<<<dim3(H_ / 128, M_ / 256), 256, gemm_smem>>>(
        aoh, aol, woh, wol, out, out, out,
        H_ / 128, 0, H_, H_, H_, H_, M_, H_);
}